// round 9
// baseline (speedup 1.0000x reference)
#include <cuda_runtime.h>
#include <cstddef>

#define NN 50000
#define EE 800000
#define ET 850000   // EE + NN self loops
#define NEG 0.2f

// ---------------- scratch (static __device__, no allocations) ----------------
__device__ __align__(16) float g_hfull[NN * 256];   // h = act @ W (layer 1/2)
__device__ __align__(16) float g_h1act[NN * 256];   // relu(gat1 out + b1)
__device__ __align__(16) float g_h2[NN * 64];       // relu(mean-head gat2 out + b2)
__device__ __align__(16) float g_hm[NN * 32];
__device__ __align__(16) float g_hs[NN * 32];
__device__ __align__(16) float g_esrc[NN * 4];      // per-node src coeff (float4 / float2 views)
__device__ __align__(16) float g_edst[NN * 4];
__device__ __align__(16) float g_e[ET * 4];         // fallback scratch only
__device__ __align__(16) float g_alpha[ET * 4];     // fallback scratch only
__device__ int g_deg[NN];
__device__ int g_rowptr[NN + 1];
__device__ int g_cursor[NN];
__device__ int g_perm[ET];   // CSR position -> original edge id
__device__ int g_srcp[ET];   // CSR position -> src node

__device__ __forceinline__ float lrelu(float v) { return v > 0.f ? v : NEG * v; }

// ---------------- CSR build ----------------
__global__ void k_zero_deg() {
    int i = blockIdx.x * blockDim.x + threadIdx.x;
    if (i < NN) g_deg[i] = 0;
}

__global__ void k_hist(const int* __restrict__ ei) {
    int e = blockIdx.x * blockDim.x + threadIdx.x;
    if (e >= ET) return;
    int d = (e < EE) ? ei[EE + e] : (e - EE);
    atomicAdd(&g_deg[d], 1);
}

// single block, 1024 threads, warp-shuffle scan
__global__ void k_scan() {
    __shared__ int wsum[32];
    __shared__ int carry;
    const int tid = threadIdx.x, lane = tid & 31, wid = tid >> 5;
    if (tid == 0) { carry = 0; g_rowptr[0] = 0; }
    __syncthreads();
    for (int base = 0; base < NN; base += 1024) {
        int i = base + tid;
        int v = (i < NN) ? g_deg[i] : 0;
        int x = v;
#pragma unroll
        for (int o = 1; o < 32; o <<= 1) {
            int t = __shfl_up_sync(0xffffffffu, x, o);
            if (lane >= o) x += t;
        }
        if (lane == 31) wsum[wid] = x;
        __syncthreads();
        if (wid == 0) {
            int y = wsum[lane];
#pragma unroll
            for (int o = 1; o < 32; o <<= 1) {
                int t = __shfl_up_sync(0xffffffffu, y, o);
                if (lane >= o) y += t;
            }
            wsum[lane] = y;
        }
        __syncthreads();
        int c = carry;
        int incl = c + (wid ? wsum[wid - 1] : 0) + x;
        if (i < NN) {
            g_rowptr[i + 1] = incl;
            g_cursor[i] = incl - v;
        }
        int total = wsum[31];
        __syncthreads();
        if (tid == 0) carry = c + total;
        __syncthreads();
    }
}

__global__ void k_scatter(const int* __restrict__ ei) {
    int e = blockIdx.x * blockDim.x + threadIdx.x;
    if (e >= ET) return;
    int sN, dN;
    if (e < EE) { sN = ei[e]; dN = ei[EE + e]; }
    else        { sN = dN = e - EE; }
    int pos = atomicAdd(&g_cursor[dN], 1);
    g_perm[pos] = e;
    g_srcp[pos] = sN;
}

// ---------------- SGEMM: C[M,N] = A[M,K] @ B[K,N], 128x64 tile, 8x4 micro ----------------
#define BK 16
__global__ __launch_bounds__(256) void k_sgemm(const float* __restrict__ A,
                                               const float* __restrict__ B,
                                               float* __restrict__ C,
                                               int M, int N, int K) {
    __shared__ float As[BK][132];
    __shared__ float Bs[BK][68];
    const int tid = threadIdx.x;
    const int bm = blockIdx.y * 128, bn = blockIdx.x * 64;
    const int aRow = tid >> 1, aCol = (tid & 1) * 8;   // A tile: 128 rows x 16 k
    const int bRow = tid >> 4, bCol = (tid & 15) * 4;  // B tile: 16 k x 64 n
    const int tx = tid & 15, ty = tid >> 4;
    const int gr = bm + aRow;
    const float* Ap = A + (size_t)gr * K;
    const float* Bp = B + (size_t)bRow * N + bn + bCol;

    float4 pa0, pa1, pb;
    if (gr < M) {
        pa0 = *(const float4*)(Ap + aCol);
        pa1 = *(const float4*)(Ap + aCol + 4);
    } else { pa0 = pa1 = make_float4(0.f, 0.f, 0.f, 0.f); }
    pb = *(const float4*)(Bp);

    float acc[8][4] = {};
    const int nt = K / BK;
    for (int kt = 0; kt < nt; kt++) {
        As[aCol + 0][aRow] = pa0.x; As[aCol + 1][aRow] = pa0.y;
        As[aCol + 2][aRow] = pa0.z; As[aCol + 3][aRow] = pa0.w;
        As[aCol + 4][aRow] = pa1.x; As[aCol + 5][aRow] = pa1.y;
        As[aCol + 6][aRow] = pa1.z; As[aCol + 7][aRow] = pa1.w;
        *(float4*)&Bs[bRow][bCol] = pb;
        __syncthreads();
        if (kt + 1 < nt) {
            int k0 = (kt + 1) * BK;
            if (gr < M) {
                pa0 = *(const float4*)(Ap + k0 + aCol);
                pa1 = *(const float4*)(Ap + k0 + aCol + 4);
            }
            pb = *(const float4*)(Bp + (size_t)k0 * N);
        }
#pragma unroll
        for (int k = 0; k < BK; k++) {
            float4 a0 = *(float4*)&As[k][ty * 8];
            float4 a1 = *(float4*)&As[k][ty * 8 + 4];
            float4 b0 = *(float4*)&Bs[k][tx * 4];
            float af[8] = {a0.x, a0.y, a0.z, a0.w, a1.x, a1.y, a1.z, a1.w};
            float bf[4] = {b0.x, b0.y, b0.z, b0.w};
#pragma unroll
            for (int i = 0; i < 8; i++)
#pragma unroll
                for (int j = 0; j < 4; j++) acc[i][j] += af[i] * bf[j];
        }
        __syncthreads();
    }
#pragma unroll
    for (int i = 0; i < 8; i++) {
        int gr2 = bm + ty * 8 + i;
        if (gr2 >= M) continue;
        *(float4*)(C + (size_t)gr2 * N + bn + tx * 4) =
            make_float4(acc[i][0], acc[i][1], acc[i][2], acc[i][3]);
    }
}

// ---------------- fused head GEMM + coef: [M,64]@Wm/Ws[64,32] + attention dots ----------------
__global__ __launch_bounds__(1024) void k_gemm2c(const float* __restrict__ A,
                                                 const float* __restrict__ Wm,
                                                 const float* __restrict__ Ws,
                                                 const float* __restrict__ ams,
                                                 const float* __restrict__ amd,
                                                 const float* __restrict__ ass,
                                                 const float* __restrict__ asd,
                                                 float* __restrict__ Cm,
                                                 float* __restrict__ Cs, int M) {
    __shared__ float Wms[64 * 32];
    __shared__ float Wss[64 * 32];
    int tid = threadIdx.x;
    for (int i = tid; i < 64 * 32; i += 1024) { Wms[i] = Wm[i]; Wss[i] = Ws[i]; }
    __syncthreads();
    int row = blockIdx.x * 32 + (tid >> 5);
    if (row >= M) return;
    int col = tid & 31;
    const float* a = A + (size_t)row * 64;
    float m = 0.f, s = 0.f;
#pragma unroll
    for (int k = 0; k < 64; k++) {
        float av = a[k];
        m += av * Wms[k * 32 + col];
        s += av * Wss[k * 32 + col];
    }
    Cm[(size_t)row * 32 + col] = m;
    Cs[(size_t)row * 32 + col] = s;
    // fused attention coefficient dots
    float p0 = m * ams[col], p1 = m * amd[col];
    float p2 = s * ass[col], p3 = s * asd[col];
#pragma unroll
    for (int o = 16; o > 0; o >>= 1) {
        p0 += __shfl_down_sync(0xffffffffu, p0, o);
        p1 += __shfl_down_sync(0xffffffffu, p1, o);
        p2 += __shfl_down_sync(0xffffffffu, p2, o);
        p3 += __shfl_down_sync(0xffffffffu, p3, o);
    }
    if (col == 0) {
        ((float2*)g_esrc)[row] = make_float2(p0, p2);
        ((float2*)g_edst)[row] = make_float2(p1, p3);
    }
}

// ---------------- attention coefficients, warp per node (H=4,C=64) ----------------
__global__ void k_coef4w(const float* __restrict__ hfull, const float* __restrict__ as_,
                         const float* __restrict__ ad_) {
    int n = blockIdx.x * 8 + (threadIdx.x >> 5);
    if (n >= NN) return;
    int lane = threadIdx.x & 31;
    const float4* hp = (const float4*)(hfull + (size_t)n * 256) + lane * 2;
    float4 v0 = hp[0], v1 = hp[1];
    const float4* ap = (const float4*)as_ + lane * 2;
    const float4* dp = (const float4*)ad_ + lane * 2;
    float4 s0 = ap[0], s1 = ap[1];
    float4 d0 = dp[0], d1 = dp[1];
    float ps = v0.x * s0.x + v0.y * s0.y + v0.z * s0.z + v0.w * s0.w
             + v1.x * s1.x + v1.y * s1.y + v1.z * s1.z + v1.w * s1.w;
    float pd = v0.x * d0.x + v0.y * d0.y + v0.z * d0.z + v0.w * d0.w
             + v1.x * d1.x + v1.y * d1.y + v1.z * d1.z + v1.w * d1.w;
#pragma unroll
    for (int o = 4; o > 0; o >>= 1) {
        ps += __shfl_down_sync(0xffffffffu, ps, o);
        pd += __shfl_down_sync(0xffffffffu, pd, o);
    }
    if ((lane & 7) == 0) {
        int h = lane >> 3;
        g_esrc[n * 4 + h] = ps;
        g_edst[n * 4 + h] = pd;
    }
}

// ---------------- fused GAT layer: logits + softmax + aggregation, block per node ----------------
__global__ __launch_bounds__(256) void k_gat4(const float* __restrict__ hfull,
                                              const float* __restrict__ bias,
                                              float* __restrict__ out,
                                              float* __restrict__ aw_out, int concat) {
    __shared__ int   ssrc[256];
    __shared__ float se[256 * 4];     // per-edge logits -> exp -> alpha (head-interleaved)
    __shared__ float4 swred[8];
    __shared__ float4 sbc;
    __shared__ float sm[256];

    const int n = blockIdx.x, t = threadIdx.x;
    const int lane = t & 31, wid = t >> 5;
    const int s = g_rowptr[n], en = g_rowptr[n + 1];
    const int deg = en - s;
    const float4 ed = ((const float4*)g_edst)[n];
    const int head = t >> 6;
    float acc = 0.f;

    if (deg <= 256) {
        // ---- logits (one thread per edge) ----
        float4 v = make_float4(-1e30f, -1e30f, -1e30f, -1e30f);
        if (t < deg) {
            int src = g_srcp[s + t];
            ssrc[t] = src;
            float4 es = ((const float4*)g_esrc)[src];
            v.x = lrelu(es.x + ed.x); v.y = lrelu(es.y + ed.y);
            v.z = lrelu(es.z + ed.z); v.w = lrelu(es.w + ed.w);
        }
        // ---- block max ----
        float4 r = v;
#pragma unroll
        for (int o = 16; o > 0; o >>= 1) {
            r.x = fmaxf(r.x, __shfl_xor_sync(0xffffffffu, r.x, o));
            r.y = fmaxf(r.y, __shfl_xor_sync(0xffffffffu, r.y, o));
            r.z = fmaxf(r.z, __shfl_xor_sync(0xffffffffu, r.z, o));
            r.w = fmaxf(r.w, __shfl_xor_sync(0xffffffffu, r.w, o));
        }
        if (lane == 0) swred[wid] = r;
        __syncthreads();
        if (t == 0) {
            float4 m = swred[0];
#pragma unroll
            for (int i = 1; i < 8; i++) {
                m.x = fmaxf(m.x, swred[i].x); m.y = fmaxf(m.y, swred[i].y);
                m.z = fmaxf(m.z, swred[i].z); m.w = fmaxf(m.w, swred[i].w);
            }
            sbc = m;
        }
        __syncthreads();
        float4 mx = sbc;
        // ---- exp ----
        float4 e = make_float4(0.f, 0.f, 0.f, 0.f);
        if (t < deg) {
            e.x = __expf(v.x - mx.x); e.y = __expf(v.y - mx.y);
            e.z = __expf(v.z - mx.z); e.w = __expf(v.w - mx.w);
        }
        // ---- block sum ----
        float4 r2 = e;
#pragma unroll
        for (int o = 16; o > 0; o >>= 1) {
            r2.x += __shfl_xor_sync(0xffffffffu, r2.x, o);
            r2.y += __shfl_xor_sync(0xffffffffu, r2.y, o);
            r2.z += __shfl_xor_sync(0xffffffffu, r2.z, o);
            r2.w += __shfl_xor_sync(0xffffffffu, r2.w, o);
        }
        if (lane == 0) swred[wid] = r2;
        __syncthreads();
        if (t == 0) {
            float4 sum = swred[0];
#pragma unroll
            for (int i = 1; i < 8; i++) {
                sum.x += swred[i].x; sum.y += swred[i].y;
                sum.z += swred[i].z; sum.w += swred[i].w;
            }
            sbc = make_float4(1.f / (sum.x + 1e-16f), 1.f / (sum.y + 1e-16f),
                              1.f / (sum.z + 1e-16f), 1.f / (sum.w + 1e-16f));
        }
        __syncthreads();
        float4 inv = sbc;
        if (t < deg) {
            float4 a = make_float4(e.x * inv.x, e.y * inv.y, e.z * inv.z, e.w * inv.w);
            se[t * 4 + 0] = a.x; se[t * 4 + 1] = a.y;
            se[t * 4 + 2] = a.z; se[t * 4 + 3] = a.w;
            ((float4*)aw_out)[g_perm[s + t]] = a;
        }
        __syncthreads();
        // ---- aggregation (feature-parallel) ----
        float acc1 = 0.f;
        int i = 0;
#pragma unroll 4
        for (; i + 1 < deg; i += 2) {
            acc  += se[i * 4 + head]       * hfull[(size_t)ssrc[i] * 256 + t];
            acc1 += se[(i + 1) * 4 + head] * hfull[(size_t)ssrc[i + 1] * 256 + t];
        }
        if (i < deg)
            acc += se[i * 4 + head] * hfull[(size_t)ssrc[i] * 256 + t];
        acc += acc1;
    } else {
        // ---- fallback: general degree, global scratch (rare) ----
        float4 vmax = make_float4(-1e30f, -1e30f, -1e30f, -1e30f);
        for (int j = s + t; j < en; j += 256) {
            int src = g_srcp[j];
            float4 es = ((const float4*)g_esrc)[src];
            float4 v;
            v.x = lrelu(es.x + ed.x); v.y = lrelu(es.y + ed.y);
            v.z = lrelu(es.z + ed.z); v.w = lrelu(es.w + ed.w);
            ((float4*)g_e)[j] = v;
            vmax.x = fmaxf(vmax.x, v.x); vmax.y = fmaxf(vmax.y, v.y);
            vmax.z = fmaxf(vmax.z, v.z); vmax.w = fmaxf(vmax.w, v.w);
        }
        float4 r = vmax;
#pragma unroll
        for (int o = 16; o > 0; o >>= 1) {
            r.x = fmaxf(r.x, __shfl_xor_sync(0xffffffffu, r.x, o));
            r.y = fmaxf(r.y, __shfl_xor_sync(0xffffffffu, r.y, o));
            r.z = fmaxf(r.z, __shfl_xor_sync(0xffffffffu, r.z, o));
            r.w = fmaxf(r.w, __shfl_xor_sync(0xffffffffu, r.w, o));
        }
        if (lane == 0) swred[wid] = r;
        __syncthreads();
        if (t == 0) {
            float4 m = swred[0];
            for (int i = 1; i < 8; i++) {
                m.x = fmaxf(m.x, swred[i].x); m.y = fmaxf(m.y, swred[i].y);
                m.z = fmaxf(m.z, swred[i].z); m.w = fmaxf(m.w, swred[i].w);
            }
            sbc = m;
        }
        __syncthreads();
        float4 mx = sbc;
        float4 vsum = make_float4(0.f, 0.f, 0.f, 0.f);
        for (int j = s + t; j < en; j += 256) {
            float4 v = ((float4*)g_e)[j];
            v.x = __expf(v.x - mx.x); v.y = __expf(v.y - mx.y);
            v.z = __expf(v.z - mx.z); v.w = __expf(v.w - mx.w);
            ((float4*)g_e)[j] = v;
            vsum.x += v.x; vsum.y += v.y; vsum.z += v.z; vsum.w += v.w;
        }
        float4 r2 = vsum;
#pragma unroll
        for (int o = 16; o > 0; o >>= 1) {
            r2.x += __shfl_xor_sync(0xffffffffu, r2.x, o);
            r2.y += __shfl_xor_sync(0xffffffffu, r2.y, o);
            r2.z += __shfl_xor_sync(0xffffffffu, r2.z, o);
            r2.w += __shfl_xor_sync(0xffffffffu, r2.w, o);
        }
        if (lane == 0) swred[wid] = r2;
        __syncthreads();
        if (t == 0) {
            float4 sum = swred[0];
            for (int i = 1; i < 8; i++) {
                sum.x += swred[i].x; sum.y += swred[i].y;
                sum.z += swred[i].z; sum.w += swred[i].w;
            }
            sbc = make_float4(1.f / (sum.x + 1e-16f), 1.f / (sum.y + 1e-16f),
                              1.f / (sum.z + 1e-16f), 1.f / (sum.w + 1e-16f));
        }
        __syncthreads();
        float4 inv = sbc;
        for (int j = s + t; j < en; j += 256) {
            float4 v = ((float4*)g_e)[j];
            float4 a = make_float4(v.x * inv.x, v.y * inv.y, v.z * inv.z, v.w * inv.w);
            ((float4*)g_alpha)[j] = a;
            ((float4*)aw_out)[g_perm[j]] = a;
        }
        __syncthreads();
        for (int base = s; base < en; base += 256) {
            int cnt = min(256, en - base);
            __syncthreads();
            if (t < cnt) {
                ssrc[t] = g_srcp[base + t];
                float4 a = ((float4*)g_alpha)[base + t];
                se[t * 4 + 0] = a.x; se[t * 4 + 1] = a.y;
                se[t * 4 + 2] = a.z; se[t * 4 + 3] = a.w;
            }
            __syncthreads();
            for (int i = 0; i < cnt; i++)
                acc += se[i * 4 + head] * hfull[(size_t)ssrc[i] * 256 + t];
        }
    }

    // ---- epilogue ----
    if (concat) {
        out[(size_t)n * 256 + t] = fmaxf(acc + bias[t], 0.f);
    } else {
        sm[t] = acc;
        __syncthreads();
        if (t < 64) {
            float v = (sm[t] + sm[t + 64] + sm[t + 128] + sm[t + 192]) * 0.25f + bias[t];
            out[(size_t)n * 64 + t] = fmaxf(v, 0.f);
        }
    }
}

// ---------------- fused head GAT: softmax (regs) + aggregation, warp per node, 2 channels ----------------
__global__ void k_gat2(const float* __restrict__ hm, const float* __restrict__ hs,
                       const float* __restrict__ bm, const float* __restrict__ bs,
                       float* __restrict__ zm, float* __restrict__ zs,
                       float* __restrict__ awm, float* __restrict__ aws) {
    __shared__ int    wsrc[8][64];
    __shared__ float2 walf[8][64];
    int w = threadIdx.x >> 5;
    int n = blockIdx.x * 8 + w;
    if (n >= NN) return;
    int lane = threadIdx.x & 31;
    int s = g_rowptr[n], en = g_rowptr[n + 1];
    int deg = en - s;
    float2 ed = ((const float2*)g_edst)[n];
    float accm = 0.f, accs = 0.f;

    if (deg <= 64) {
        int j0 = s + lane, j1 = s + 32 + lane;
        int s0 = (j0 < en) ? g_srcp[j0] : 0;
        int s1 = (j1 < en) ? g_srcp[j1] : 0;
        float2 es0 = ((const float2*)g_esrc)[s0];
        float2 es1 = ((const float2*)g_esrc)[s1];
        float2 v0 = make_float2(lrelu(es0.x + ed.x), lrelu(es0.y + ed.y));
        float2 v1 = make_float2(lrelu(es1.x + ed.x), lrelu(es1.y + ed.y));
        if (j0 >= en) v0 = make_float2(-1e30f, -1e30f);
        if (j1 >= en) v1 = make_float2(-1e30f, -1e30f);
        float m0 = fmaxf(v0.x, v1.x), m1 = fmaxf(v0.y, v1.y);
#pragma unroll
        for (int o = 16; o > 0; o >>= 1) {
            m0 = fmaxf(m0, __shfl_xor_sync(0xffffffffu, m0, o));
            m1 = fmaxf(m1, __shfl_xor_sync(0xffffffffu, m1, o));
        }
        float2 x0 = make_float2(0.f, 0.f), x1 = make_float2(0.f, 0.f);
        if (j0 < en) x0 = make_float2(__expf(v0.x - m0), __expf(v0.y - m1));
        if (j1 < en) x1 = make_float2(__expf(v1.x - m0), __expf(v1.y - m1));
        float su0 = x0.x + x1.x, su1 = x0.y + x1.y;
#pragma unroll
        for (int o = 16; o > 0; o >>= 1) {
            su0 += __shfl_xor_sync(0xffffffffu, su0, o);
            su1 += __shfl_xor_sync(0xffffffffu, su1, o);
        }
        float i0 = 1.f / (su0 + 1e-16f), i1 = 1.f / (su1 + 1e-16f);
        if (j0 < en) {
            float2 a = make_float2(x0.x * i0, x0.y * i1);
            int p = g_perm[j0];
            awm[p] = a.x; aws[p] = a.y;
            wsrc[w][lane] = s0; walf[w][lane] = a;
        }
        if (j1 < en) {
            float2 a = make_float2(x1.x * i0, x1.y * i1);
            int p = g_perm[j1];
            awm[p] = a.x; aws[p] = a.y;
            wsrc[w][32 + lane] = s1; walf[w][32 + lane] = a;
        }
        __syncwarp();
        // aggregation: lane = feature
        float am1 = 0.f, as1 = 0.f;
        int i = 0;
#pragma unroll 4
        for (; i + 1 < deg; i += 2) {
            int sc0 = wsrc[w][i];     float2 a0 = walf[w][i];
            int sc1 = wsrc[w][i + 1]; float2 a1 = walf[w][i + 1];
            accm += a0.x * hm[(size_t)sc0 * 32 + lane];
            accs += a0.y * hs[(size_t)sc0 * 32 + lane];
            am1  += a1.x * hm[(size_t)sc1 * 32 + lane];
            as1  += a1.y * hs[(size_t)sc1 * 32 + lane];
        }
        if (i < deg) {
            int sc = wsrc[w][i]; float2 a = walf[w][i];
            accm += a.x * hm[(size_t)sc * 32 + lane];
            accs += a.y * hs[(size_t)sc * 32 + lane];
        }
        accm += am1; accs += as1;
    } else {
        // fallback: general degree via global scratch (rare)
        float m0 = -1e30f, m1 = -1e30f;
        for (int j = s + lane; j < en; j += 32) {
            float2 es = ((const float2*)g_esrc)[g_srcp[j]];
            float2 v = make_float2(lrelu(es.x + ed.x), lrelu(es.y + ed.y));
            ((float2*)g_e)[j] = v;
            m0 = fmaxf(m0, v.x); m1 = fmaxf(m1, v.y);
        }
#pragma unroll
        for (int o = 16; o > 0; o >>= 1) {
            m0 = fmaxf(m0, __shfl_xor_sync(0xffffffffu, m0, o));
            m1 = fmaxf(m1, __shfl_xor_sync(0xffffffffu, m1, o));
        }
        float su0 = 0.f, su1 = 0.f;
        for (int j = s + lane; j < en; j += 32) {
            float2 v = ((float2*)g_e)[j];
            v.x = __expf(v.x - m0); v.y = __expf(v.y - m1);
            ((float2*)g_e)[j] = v;
            su0 += v.x; su1 += v.y;
        }
#pragma unroll
        for (int o = 16; o > 0; o >>= 1) {
            su0 += __shfl_xor_sync(0xffffffffu, su0, o);
            su1 += __shfl_xor_sync(0xffffffffu, su1, o);
        }
        float i0 = 1.f / (su0 + 1e-16f), i1 = 1.f / (su1 + 1e-16f);
        for (int j = s + lane; j < en; j += 32) {
            float2 v = ((float2*)g_e)[j];
            float2 a = make_float2(v.x * i0, v.y * i1);
            ((float2*)g_alpha)[j] = a;
            int p = g_perm[j];
            awm[p] = a.x; aws[p] = a.y;
        }
        __syncwarp();
        for (int j = s; j < en; j++) {
            int sc = g_srcp[j];
            float2 a = ((float2*)g_alpha)[j];
            accm += a.x * hm[(size_t)sc * 32 + lane];
            accs += a.y * hs[(size_t)sc * 32 + lane];
        }
    }
    zm[(size_t)n * 32 + lane] = accm + bm[lane];
    zs[(size_t)n * 32 + lane] = accs + bs[lane];
}

// ---------------- driver ----------------
extern "C" void kernel_launch(void* const* d_in, const int* in_sizes, int n_in,
                              void* d_out, int out_size) {
    const float* x   = (const float*)d_in[0];
    const int*   ei  = (const int*)d_in[1];
    const float* W1  = (const float*)d_in[2];
    const float* a1s = (const float*)d_in[3];
    const float* a1d = (const float*)d_in[4];
    const float* b1  = (const float*)d_in[5];
    const float* W2  = (const float*)d_in[6];
    const float* a2s = (const float*)d_in[7];
    const float* a2d = (const float*)d_in[8];
    const float* b2  = (const float*)d_in[9];
    const float* Wm  = (const float*)d_in[10];
    const float* ams = (const float*)d_in[11];
    const float* amd = (const float*)d_in[12];
    const float* bm  = (const float*)d_in[13];
    const float* Ws  = (const float*)d_in[14];
    const float* ass = (const float*)d_in[15];
    const float* asd = (const float*)d_in[16];
    const float* bs  = (const float*)d_in[17];

    float* out = (float*)d_out;
    float* zm  = out;                 // [N,32]
    float* zs  = out + 1600000;       // [N,32]
    float* aw1 = out + 3200000;       // [ET,4]
    float* aw2 = out + 6600000;       // [ET,4]
    float* awm = out + 10000000;      // [ET,1]
    float* aws = out + 10850000;      // [ET,1]

    const int EB  = (ET + 255) / 256;
    const int NB8 = (NN + 7) / 8;
    dim3 gg(4, (NN + 127) / 128);     // 64-col tiles x 128-row tiles

    // launch 0..2
    k_zero_deg<<<(NN + 255) / 256, 256>>>();
    k_hist<<<EB, 256>>>(ei);
    k_sgemm<<<gg, 256>>>(x, W1, g_hfull, NN, 256, 256);
    // launch 3: scan  <-- ncu capture slot probe
    k_scan<<<1, 1024>>>();
    k_scatter<<<EB, 256>>>(ei);

    // ---- layer 1 ----
    k_coef4w<<<NB8, 256>>>(g_hfull, a1s, a1d);
    k_gat4<<<NN, 256>>>(g_hfull, b1, g_h1act, aw1, 1);

    // ---- layer 2 ----
    k_sgemm<<<gg, 256>>>(g_h1act, W2, g_hfull, NN, 256, 256);
    k_coef4w<<<NB8, 256>>>(g_hfull, a2s, a2d);
    k_gat4<<<NN, 256>>>(g_hfull, b2, g_h2, aw2, 0);

    // ---- heads (both channels fused) ----
    k_gemm2c<<<(NN + 31) / 32, 1024>>>(g_h2, Wm, Ws, ams, amd, ass, asd, g_hm, g_hs, NN);
    k_gat2<<<NB8, 256>>>(g_hm, g_hs, bm, bs, zm, zs, awm, aws);
}

// round 10
// speedup vs baseline: 1.1739x; 1.1739x over previous
#include <cuda_runtime.h>
#include <cstddef>

#define NN 50000
#define EE 800000
#define ET 850000   // EE + NN self loops
#define NEG 0.2f

// ---------------- scratch (static __device__, no allocations) ----------------
__device__ __align__(16) float g_hfull[NN * 256];   // h = act @ W (layer 1/2)
__device__ __align__(16) float g_h1act[NN * 256];   // relu(gat1 out + b1); probe scribbles here first
__device__ __align__(16) float g_h2[NN * 64];       // relu(mean-head gat2 out + b2)
__device__ __align__(16) float g_hm[NN * 32];
__device__ __align__(16) float g_hs[NN * 32];
__device__ __align__(16) float g_esrc[NN * 4];      // reused as float2 for heads
__device__ __align__(16) float g_edst[NN * 4];
__device__ __align__(16) float g_e[ET * 4];         // logits/exp scratch
__device__ __align__(16) float g_alpha[ET * 4];     // alpha in CSR order
__device__ int g_deg[NN];
__device__ int g_rowptr[NN + 1];
__device__ int g_cursor[NN];
__device__ int g_perm[ET];   // CSR position -> original edge id
__device__ int g_srcp[ET];   // CSR position -> src node

__device__ __forceinline__ float lrelu(float v) { return v > 0.f ? v : NEG * v; }

// ---------------- CSR build ----------------
__global__ void k_zero_deg() {
    int i = blockIdx.x * blockDim.x + threadIdx.x;
    if (i < NN) g_deg[i] = 0;
}

__global__ void k_hist(const int* __restrict__ ei) {
    int e = blockIdx.x * blockDim.x + threadIdx.x;
    if (e >= ET) return;
    int d = (e < EE) ? ei[EE + e] : (e - EE);
    atomicAdd(&g_deg[d], 1);
}

// single block, 1024 threads, warp-shuffle scan
__global__ void k_scan() {
    __shared__ int wsum[32];
    __shared__ int carry;
    const int tid = threadIdx.x, lane = tid & 31, wid = tid >> 5;
    if (tid == 0) { carry = 0; g_rowptr[0] = 0; }
    __syncthreads();
    for (int base = 0; base < NN; base += 1024) {
        int i = base + tid;
        int v = (i < NN) ? g_deg[i] : 0;
        int x = v;
#pragma unroll
        for (int o = 1; o < 32; o <<= 1) {
            int t = __shfl_up_sync(0xffffffffu, x, o);
            if (lane >= o) x += t;
        }
        if (lane == 31) wsum[wid] = x;
        __syncthreads();
        if (wid == 0) {
            int y = wsum[lane];
#pragma unroll
            for (int o = 1; o < 32; o <<= 1) {
                int t = __shfl_up_sync(0xffffffffu, y, o);
                if (lane >= o) y += t;
            }
            wsum[lane] = y;
        }
        __syncthreads();
        int c = carry;
        int incl = c + (wid ? wsum[wid - 1] : 0) + x;
        if (i < NN) {
            g_rowptr[i + 1] = incl;
            g_cursor[i] = incl - v;
        }
        int total = wsum[31];
        __syncthreads();
        if (tid == 0) carry = c + total;
        __syncthreads();
    }
}

__global__ void k_scatter(const int* __restrict__ ei) {
    int e = blockIdx.x * blockDim.x + threadIdx.x;
    if (e >= ET) return;
    int sN, dN;
    if (e < EE) { sN = ei[e]; dN = ei[EE + e]; }
    else        { sN = dN = e - EE; }
    int pos = atomicAdd(&g_cursor[dN], 1);
    g_perm[pos] = e;
    g_srcp[pos] = sN;
}

// ---------------- PROBE: quarter-scale clone of k_agg4's gather pattern ----------------
// Depends only on ei + g_hfull. Writes g_h1act rows [0,12500) which the real
// agg4 fully overwrites later -> outputs unaffected. Sits at launch index 3 so
// the fixed ncu capture slot measures the suspect random-row-gather pattern.
__global__ __launch_bounds__(256) void k_probe(const int* __restrict__ ei,
                                               const float* __restrict__ hfull,
                                               float* __restrict__ outp) {
    __shared__ int ssrc[16];
    __shared__ float salf[64];
    int n = blockIdx.x;               // 12500 blocks
    int t = threadIdx.x;
    int head = t >> 6;
    int base = n * 16;                // window of 16 "edges" from original src list
    if (t < 16) ssrc[t] = ei[base + t];     // random row ids in [0, NN)
    if (t < 64) salf[t] = 0.25f + 0.001f * (float)t;
    __syncthreads();
    float acc = 0.f, acc1 = 0.f;
#pragma unroll 4
    for (int i = 0; i < 16; i += 2) {
        acc  += salf[i * 4 + head]       * hfull[(size_t)ssrc[i] * 256 + t];
        acc1 += salf[(i + 1) * 4 + head] * hfull[(size_t)ssrc[i + 1] * 256 + t];
    }
    outp[(size_t)n * 256 + t] = acc + acc1;
}

// ---------------- SGEMM: C[M,N] = A[M,K] @ B[K,N], 128x128x16, double-buffered ----------------
#define BK 16
__global__ __launch_bounds__(256) void k_sgemm(const float* __restrict__ A,
                                               const float* __restrict__ B,
                                               float* __restrict__ C,
                                               int M, int N, int K) {
    __shared__ float As[BK][132];
    __shared__ float Bs[BK][132];
    const int tid = threadIdx.x;
    const int bm = blockIdx.y * 128, bn = blockIdx.x * 128;
    const int aRow = tid >> 1, aCol = (tid & 1) * 8;
    const int bRow = tid >> 4, bCol = (tid & 15) * 8;
    const int tx = tid & 15, ty = tid >> 4;
    const int gr = bm + aRow;
    const float* Ap = A + (size_t)gr * K;
    const float* Bp = B + (size_t)bRow * N + bn + bCol;

    float4 pa0, pa1, pb0, pb1;
    if (gr < M) {
        pa0 = *(const float4*)(Ap + aCol);
        pa1 = *(const float4*)(Ap + aCol + 4);
    } else { pa0 = pa1 = make_float4(0.f, 0.f, 0.f, 0.f); }
    pb0 = *(const float4*)(Bp);
    pb1 = *(const float4*)(Bp + 4);

    float acc[8][8] = {};
    const int nt = K / BK;
    for (int kt = 0; kt < nt; kt++) {
        As[aCol + 0][aRow] = pa0.x; As[aCol + 1][aRow] = pa0.y;
        As[aCol + 2][aRow] = pa0.z; As[aCol + 3][aRow] = pa0.w;
        As[aCol + 4][aRow] = pa1.x; As[aCol + 5][aRow] = pa1.y;
        As[aCol + 6][aRow] = pa1.z; As[aCol + 7][aRow] = pa1.w;
        *(float4*)&Bs[bRow][bCol]     = pb0;
        *(float4*)&Bs[bRow][bCol + 4] = pb1;
        __syncthreads();
        if (kt + 1 < nt) {
            int k0 = (kt + 1) * BK;
            if (gr < M) {
                pa0 = *(const float4*)(Ap + k0 + aCol);
                pa1 = *(const float4*)(Ap + k0 + aCol + 4);
            }
            pb0 = *(const float4*)(Bp + (size_t)k0 * N);
            pb1 = *(const float4*)(Bp + (size_t)k0 * N + 4);
        }
#pragma unroll
        for (int k = 0; k < BK; k++) {
            float4 a0 = *(float4*)&As[k][ty * 4];
            float4 a1 = *(float4*)&As[k][64 + ty * 4];
            float4 b0 = *(float4*)&Bs[k][tx * 4];
            float4 b1 = *(float4*)&Bs[k][64 + tx * 4];
            float af[8] = {a0.x, a0.y, a0.z, a0.w, a1.x, a1.y, a1.z, a1.w};
            float bf[8] = {b0.x, b0.y, b0.z, b0.w, b1.x, b1.y, b1.z, b1.w};
#pragma unroll
            for (int i = 0; i < 8; i++)
#pragma unroll
                for (int j = 0; j < 8; j++) acc[i][j] += af[i] * bf[j];
        }
        __syncthreads();
    }
#pragma unroll
    for (int i = 0; i < 8; i++) {
        int gr2 = bm + (i < 4 ? ty * 4 + i : 64 + ty * 4 + (i - 4));
        if (gr2 >= M) continue;
        float* cp = C + (size_t)gr2 * N + bn;
        *(float4*)(cp + tx * 4)      = make_float4(acc[i][0], acc[i][1], acc[i][2], acc[i][3]);
        *(float4*)(cp + 64 + tx * 4) = make_float4(acc[i][4], acc[i][5], acc[i][6], acc[i][7]);
    }
}

// ---------------- fused small GEMM: [M,64] @ Wm,Ws[64,32] -> Cm,Cs[M,32] ----------------
__global__ __launch_bounds__(1024) void k_gemm2(const float* __restrict__ A,
                                                const float* __restrict__ Wm,
                                                const float* __restrict__ Ws,
                                                float* __restrict__ Cm,
                                                float* __restrict__ Cs, int M) {
    __shared__ float Wms[64 * 32];
    __shared__ float Wss[64 * 32];
    int tid = threadIdx.x;
    for (int i = tid; i < 64 * 32; i += 1024) { Wms[i] = Wm[i]; Wss[i] = Ws[i]; }
    __syncthreads();
    int row = blockIdx.x * 32 + (tid >> 5);
    if (row >= M) return;
    int col = tid & 31;
    const float* a = A + (size_t)row * 64;
    float m = 0.f, s = 0.f;
#pragma unroll
    for (int k = 0; k < 64; k++) {
        float av = a[k];
        m += av * Wms[k * 32 + col];
        s += av * Wss[k * 32 + col];
    }
    Cm[(size_t)row * 32 + col] = m;
    Cs[(size_t)row * 32 + col] = s;
}

// ---------------- attention coefficients, warp per node (H=4,C=64) ----------------
__global__ void k_coef4w(const float* __restrict__ hfull, const float* __restrict__ as_,
                         const float* __restrict__ ad_) {
    int n = blockIdx.x * 8 + (threadIdx.x >> 5);
    if (n >= NN) return;
    int lane = threadIdx.x & 31;
    const float4* hp = (const float4*)(hfull + (size_t)n * 256) + lane * 2;
    float4 v0 = hp[0], v1 = hp[1];
    const float4* ap = (const float4*)as_ + lane * 2;
    const float4* dp = (const float4*)ad_ + lane * 2;
    float4 s0 = ap[0], s1 = ap[1];
    float4 d0 = dp[0], d1 = dp[1];
    float ps = v0.x * s0.x + v0.y * s0.y + v0.z * s0.z + v0.w * s0.w
             + v1.x * s1.x + v1.y * s1.y + v1.z * s1.z + v1.w * s1.w;
    float pd = v0.x * d0.x + v0.y * d0.y + v0.z * d0.z + v0.w * d0.w
             + v1.x * d1.x + v1.y * d1.y + v1.z * d1.z + v1.w * d1.w;
#pragma unroll
    for (int o = 4; o > 0; o >>= 1) {
        ps += __shfl_down_sync(0xffffffffu, ps, o);
        pd += __shfl_down_sync(0xffffffffu, pd, o);
    }
    if ((lane & 7) == 0) {
        int h = lane >> 3;
        g_esrc[n * 4 + h] = ps;
        g_edst[n * 4 + h] = pd;
    }
}

// ---------------- attention coefficients, both 32-feature heads at once ----------------
__global__ void k_coef1x2(const float* __restrict__ hm, const float* __restrict__ hs,
                          const float* __restrict__ ams, const float* __restrict__ amd,
                          const float* __restrict__ ass, const float* __restrict__ asd) {
    int n = blockIdx.x * 8 + (threadIdx.x >> 5);
    if (n >= NN) return;
    int lane = threadIdx.x & 31;
    float vm = hm[(size_t)n * 32 + lane];
    float vs = hs[(size_t)n * 32 + lane];
    float p0 = vm * ams[lane], p1 = vm * amd[lane];
    float p2 = vs * ass[lane], p3 = vs * asd[lane];
#pragma unroll
    for (int o = 16; o > 0; o >>= 1) {
        p0 += __shfl_down_sync(0xffffffffu, p0, o);
        p1 += __shfl_down_sync(0xffffffffu, p1, o);
        p2 += __shfl_down_sync(0xffffffffu, p2, o);
        p3 += __shfl_down_sync(0xffffffffu, p3, o);
    }
    if (lane == 0) {
        ((float2*)g_esrc)[n] = make_float2(p0, p2);
        ((float2*)g_edst)[n] = make_float2(p1, p3);
    }
}

// ---------------- segment softmax (warp per node), H=4, edge logits fused ----------------
__global__ void k_softmax4(float* __restrict__ aw_out) {
    int n = blockIdx.x * 8 + (threadIdx.x >> 5);
    if (n >= NN) return;
    int lane = threadIdx.x & 31;
    int s = g_rowptr[n], t = g_rowptr[n + 1];
    float4 ed = ((const float4*)g_edst)[n];
    float4 mx = make_float4(-1e30f, -1e30f, -1e30f, -1e30f);
    for (int j = s + lane; j < t; j += 32) {
        float4 es = ((const float4*)g_esrc)[g_srcp[j]];
        float4 v;
        v.x = lrelu(es.x + ed.x); v.y = lrelu(es.y + ed.y);
        v.z = lrelu(es.z + ed.z); v.w = lrelu(es.w + ed.w);
        ((float4*)g_e)[j] = v;
        mx.x = fmaxf(mx.x, v.x); mx.y = fmaxf(mx.y, v.y);
        mx.z = fmaxf(mx.z, v.z); mx.w = fmaxf(mx.w, v.w);
    }
#pragma unroll
    for (int o = 16; o > 0; o >>= 1) {
        mx.x = fmaxf(mx.x, __shfl_xor_sync(0xffffffffu, mx.x, o));
        mx.y = fmaxf(mx.y, __shfl_xor_sync(0xffffffffu, mx.y, o));
        mx.z = fmaxf(mx.z, __shfl_xor_sync(0xffffffffu, mx.z, o));
        mx.w = fmaxf(mx.w, __shfl_xor_sync(0xffffffffu, mx.w, o));
    }
    float4 sum = make_float4(0.f, 0.f, 0.f, 0.f);
    for (int j = s + lane; j < t; j += 32) {
        float4 v = ((const float4*)g_e)[j];
        v.x = __expf(v.x - mx.x); v.y = __expf(v.y - mx.y);
        v.z = __expf(v.z - mx.z); v.w = __expf(v.w - mx.w);
        ((float4*)g_e)[j] = v;
        sum.x += v.x; sum.y += v.y; sum.z += v.z; sum.w += v.w;
    }
#pragma unroll
    for (int o = 16; o > 0; o >>= 1) {
        sum.x += __shfl_xor_sync(0xffffffffu, sum.x, o);
        sum.y += __shfl_xor_sync(0xffffffffu, sum.y, o);
        sum.z += __shfl_xor_sync(0xffffffffu, sum.z, o);
        sum.w += __shfl_xor_sync(0xffffffffu, sum.w, o);
    }
    float4 inv;
    inv.x = 1.f / (sum.x + 1e-16f); inv.y = 1.f / (sum.y + 1e-16f);
    inv.z = 1.f / (sum.z + 1e-16f); inv.w = 1.f / (sum.w + 1e-16f);
    for (int j = s + lane; j < t; j += 32) {
        float4 v = ((const float4*)g_e)[j];
        float4 a = make_float4(v.x * inv.x, v.y * inv.y, v.z * inv.z, v.w * inv.w);
        ((float4*)g_alpha)[j] = a;
        ((float4*)aw_out)[g_perm[j]] = a;
    }
}

// ---------------- segment softmax, 2 channels (mean + log_std heads) ----------------
__global__ void k_softmax2(float* __restrict__ awm, float* __restrict__ aws) {
    int n = blockIdx.x * 8 + (threadIdx.x >> 5);
    if (n >= NN) return;
    int lane = threadIdx.x & 31;
    int s = g_rowptr[n], t = g_rowptr[n + 1];
    float2 ed = ((const float2*)g_edst)[n];
    float mx0 = -1e30f, mx1 = -1e30f;
    for (int j = s + lane; j < t; j += 32) {
        float2 es = ((const float2*)g_esrc)[g_srcp[j]];
        float2 v = make_float2(lrelu(es.x + ed.x), lrelu(es.y + ed.y));
        ((float2*)g_e)[j] = v;
        mx0 = fmaxf(mx0, v.x); mx1 = fmaxf(mx1, v.y);
    }
#pragma unroll
    for (int o = 16; o > 0; o >>= 1) {
        mx0 = fmaxf(mx0, __shfl_xor_sync(0xffffffffu, mx0, o));
        mx1 = fmaxf(mx1, __shfl_xor_sync(0xffffffffu, mx1, o));
    }
    float s0 = 0.f, s1 = 0.f;
    for (int j = s + lane; j < t; j += 32) {
        float2 v = ((float2*)g_e)[j];
        v.x = __expf(v.x - mx0); v.y = __expf(v.y - mx1);
        ((float2*)g_e)[j] = v;
        s0 += v.x; s1 += v.y;
    }
#pragma unroll
    for (int o = 16; o > 0; o >>= 1) {
        s0 += __shfl_xor_sync(0xffffffffu, s0, o);
        s1 += __shfl_xor_sync(0xffffffffu, s1, o);
    }
    float i0 = 1.f / (s0 + 1e-16f), i1 = 1.f / (s1 + 1e-16f);
    for (int j = s + lane; j < t; j += 32) {
        float2 v = ((float2*)g_e)[j];
        float2 a = make_float2(v.x * i0, v.y * i1);
        ((float2*)g_alpha)[j] = a;
        int p = g_perm[j];
        awm[p] = a.x;
        aws[p] = a.y;
    }
}

// ---------------- aggregation, 256-feature layers, SMEM-staged edge tiles ----------------
__global__ __launch_bounds__(256) void k_agg4(const float* __restrict__ hfull,
                                              const float* __restrict__ bias,
                                              float* __restrict__ out, int concat) {
    __shared__ int ssrc[64];
    __shared__ float salf[256];
    int n = blockIdx.x;
    int t = threadIdx.x;
    int head = t >> 6;
    int s = g_rowptr[n], e0 = g_rowptr[n + 1];
    float acc = 0.f;
    for (int base = s; base < e0; base += 64) {
        int cnt = min(64, e0 - base);
        __syncthreads();
        if (t < cnt) ssrc[t] = g_srcp[base + t];
        if (t < cnt * 4) salf[t] = g_alpha[(size_t)base * 4 + t];
        __syncthreads();
#pragma unroll 8
        for (int i = 0; i < cnt; i++)
            acc += salf[i * 4 + head] * hfull[(size_t)ssrc[i] * 256 + t];
    }
    if (concat) {
        out[(size_t)n * 256 + t] = fmaxf(acc + bias[t], 0.f);
    } else {
        __shared__ float sm[256];
        sm[t] = acc;
        __syncthreads();
        if (t < 64) {
            float v = (sm[t] + sm[t + 64] + sm[t + 128] + sm[t + 192]) * 0.25f + bias[t];
            out[(size_t)n * 64 + t] = fmaxf(v, 0.f);
        }
    }
}

// ---------------- aggregation, both 32-feature heads (warp per node) ----------------
__global__ void k_agg2(const float* __restrict__ hm, const float* __restrict__ hs,
                       const float* __restrict__ bm, const float* __restrict__ bs,
                       float* __restrict__ zm, float* __restrict__ zs) {
    int n = blockIdx.x * 8 + (threadIdx.x >> 5);
    if (n >= NN) return;
    int lane = threadIdx.x & 31;
    int s = g_rowptr[n], e0 = g_rowptr[n + 1];
    float am = 0.f, as_ = 0.f;
#pragma unroll 4
    for (int j = s; j < e0; j++) {
        int src = g_srcp[j];
        float2 a = ((const float2*)g_alpha)[j];
        am  += a.x * hm[(size_t)src * 32 + lane];
        as_ += a.y * hs[(size_t)src * 32 + lane];
    }
    zm[(size_t)n * 32 + lane] = am + bm[lane];
    zs[(size_t)n * 32 + lane] = as_ + bs[lane];
}

// ---------------- driver ----------------
extern "C" void kernel_launch(void* const* d_in, const int* in_sizes, int n_in,
                              void* d_out, int out_size) {
    const float* x   = (const float*)d_in[0];
    const int*   ei  = (const int*)d_in[1];
    const float* W1  = (const float*)d_in[2];
    const float* a1s = (const float*)d_in[3];
    const float* a1d = (const float*)d_in[4];
    const float* b1  = (const float*)d_in[5];
    const float* W2  = (const float*)d_in[6];
    const float* a2s = (const float*)d_in[7];
    const float* a2d = (const float*)d_in[8];
    const float* b2  = (const float*)d_in[9];
    const float* Wm  = (const float*)d_in[10];
    const float* ams = (const float*)d_in[11];
    const float* amd = (const float*)d_in[12];
    const float* bm  = (const float*)d_in[13];
    const float* Ws  = (const float*)d_in[14];
    const float* ass = (const float*)d_in[15];
    const float* asd = (const float*)d_in[16];
    const float* bs  = (const float*)d_in[17];

    float* out = (float*)d_out;
    float* zm  = out;                 // [N,32]
    float* zs  = out + 1600000;       // [N,32]
    float* aw1 = out + 3200000;       // [ET,4]
    float* aw2 = out + 6600000;       // [ET,4]
    float* awm = out + 10000000;      // [ET,1]
    float* aws = out + 10850000;      // [ET,1]

    const int EB  = (ET + 255) / 256;
    const int NB8 = (NN + 7) / 8;
    dim3 gg(2, (NN + 127) / 128);

    // launches 0..2 (sgemm has no CSR dependency)
    k_zero_deg<<<(NN + 255) / 256, 256>>>();
    k_hist<<<EB, 256>>>(ei);
    k_sgemm<<<gg, 256>>>(x, W1, g_hfull, NN, 256, 256);

    // launch 3: PROBE  <-- lands in the fixed ncu capture slot.
    // Quarter-scale clone of agg4's random-row gather; output later overwritten.
    k_probe<<<12500, 256>>>(ei, g_hfull, g_h1act);

    // CSR back half
    k_scan<<<1, 1024>>>();
    k_scatter<<<EB, 256>>>(ei);

    // ---- layer 1: 256 -> 4x64, concat ----
    k_coef4w<<<NB8, 256>>>(g_hfull, a1s, a1d);
    k_softmax4<<<NB8, 256>>>(aw1);
    k_agg4<<<NN, 256>>>(g_hfull, b1, g_h1act, 1);

    // ---- layer 2: 256 -> 4x64, mean over heads ----
    k_sgemm<<<gg, 256>>>(g_h1act, W2, g_hfull, NN, 256, 256);
    k_coef4w<<<NB8, 256>>>(g_hfull, a2s, a2d);
    k_softmax4<<<NB8, 256>>>(aw2);
    k_agg4<<<NN, 256>>>(g_hfull, b2, g_h2, 0);

    // ---- heads: 64 -> 32 (both at once), H=1 x 2 channels ----
    k_gemm2<<<(NN + 31) / 32, 1024>>>(g_h2, Wm, Ws, g_hm, g_hs, NN);
    k_coef1x2<<<NB8, 256>>>(g_hm, g_hs, ams, amd, ass, asd);
    k_softmax2<<<NB8, 256>>>(awm, aws);
    k_agg2<<<NB8, 256>>>(g_hm, g_hs, bm, bs, zm, zs);
}